// round 2
// baseline (speedup 1.0000x reference)
#include <cuda_runtime.h>
#include <stdint.h>

#define BB 2
#define NN 2048
#define TK 8
#define NF 64
#define NNODES (BB*NN)
#define NE (NNODES*TK)

// ---------------- device scratch (no allocations allowed) ----------------
__device__ unsigned char g_mask[NNODES];
__device__ unsigned char g_tmask[NNODES];
__device__ int   g_send[NE];          // sender idx within batch, -1 = invalid
__device__ int   g_cnt[NNODES];       // # valid edges per receiver (prefix)
__device__ float g_A[NE*NF];          // rel_enc, then (rp_w[0:64]^T rel_enc + rp_b)
__device__ float g_penc[NNODES*NF];   // particle encoder output
__device__ float g_q[NNODES*NF];      // pp_w[0:64]^T p_enc + pp_b
__device__ float g_eff0[NNODES*NF];
__device__ float g_eff1[NNODES*NF];

// ---------------- K0: normalize masks (runtime dtype detection) -------------
// mask is all-true in this dataset; tool_mask has first N/20 (=102) true.
// First 32-bit word therefore distinguishes the storage dtype:
//   u8  storage -> 0x01010101
//   i32 storage -> 0x00000001
//   f32 storage -> 0x3f800000
__device__ __forceinline__ unsigned char mask_elem(const unsigned char* p, int i) {
    unsigned w0 = *(const unsigned*)p;
    if (w0 == 0x01010101u)            return p[i] != 0;                       // u8/bool
    if (w0 == 0x3f800000u)            return ((const float*)p)[i] != 0.f;     // f32
    /* default int32 */               return ((const int*)p)[i] != 0;         // i32
}
__global__ __launch_bounds__(256) void k_masks(
    const unsigned char* __restrict__ mask_raw,
    const unsigned char* __restrict__ tmask_raw)
{
    int i = blockIdx.x*256 + threadIdx.x;
    if (i < NNODES) {
        g_mask[i]  = mask_elem(mask_raw, i);
        g_tmask[i] = mask_elem(tmask_raw, i);
    }
}

// ---------------- K1: edge construction (8-NN with threshold) ----------------
// 8 warps/block, 1 warp per receiver node. grid = NNODES/8 = 512
__global__ __launch_bounds__(256) void k_edges(
    const float* __restrict__ states)
{
    __shared__ float s_st[NN*3];
    __shared__ unsigned char s_m[NN];
    int b  = blockIdx.x / (NN/8);
    int i0 = (blockIdx.x % (NN/8)) * 8;
    const float* stb = states + (size_t)b*NN*3;
    for (int t = threadIdx.x; t < NN*3; t += 256) s_st[t] = stb[t];
    for (int t = threadIdx.x; t < NN;   t += 256) s_m[t]  = g_mask[b*NN + t];
    __syncthreads();

    const float TH2 = 0.12f * 0.12f;

    int w = threadIdx.x >> 5, lane = threadIdx.x & 31;
    int i = i0 + w;
    int node = b*NN + i;
    // tool receivers (or unmasked receivers) have zero valid edges
    bool recv_ok = (g_mask[node] != 0) && (g_tmask[node] == 0);

    unsigned long long keys[TK];
#pragma unroll
    for (int k = 0; k < TK; k++) keys[k] = ~0ULL;

    if (recv_ok) {
        float xi = s_st[i*3+0], yi = s_st[i*3+1], zi = s_st[i*3+2];
        unsigned long long curmax = ~0ULL; int maxslot = 0;
        for (int j = lane; j < NN; j += 32) {
            float dx = xi - s_st[j*3+0];
            float dy = yi - s_st[j*3+1];
            float dz = zi - s_st[j*3+2];
            float d2 = fmaf(dx, dx, fmaf(dy, dy, dz*dz));
            if (!s_m[j]) d2 = 1e10f;   // non-tool receiver: t12 is always false
            unsigned long long key =
                ((unsigned long long)__float_as_uint(d2) << 32) | (unsigned)j;
            if (key < curmax) {
                keys[maxslot] = key;
                curmax = keys[0]; maxslot = 0;
#pragma unroll
                for (int k = 1; k < TK; k++)
                    if (keys[k] > curmax) { curmax = keys[k]; maxslot = k; }
            }
        }
    }

    // warp-wide 8x min-extraction (keys unique: idx embedded in low bits,
    // ties break to lower j exactly like jax.lax.top_k)
    int cnt = 0;
#pragma unroll 1
    for (int r = 0; r < TK; r++) {
        unsigned long long mymin = keys[0]; int mslot = 0;
#pragma unroll
        for (int k = 1; k < TK; k++)
            if (keys[k] < mymin) { mymin = keys[k]; mslot = k; }
        unsigned long long v = mymin;
#pragma unroll
        for (int off = 16; off; off >>= 1) {
            unsigned long long o = __shfl_down_sync(0xffffffffu, v, off);
            if (o < v) v = o;
        }
        v = __shfl_sync(0xffffffffu, v, 0);
        if (v == mymin && v != ~0ULL) keys[mslot] = ~0ULL;  // owner consumes
        if (lane == 0) {
            float d2 = __uint_as_float((unsigned)(v >> 32));
            int j = (int)(v & 0xffffffffULL);
            bool valid = (v != ~0ULL) && (d2 < TH2);
            g_send[node*TK + r] = valid ? j : -1;
            cnt += valid ? 1 : 0;
        }
    }
    if (lane == 0) g_cnt[node] = cnt;
}

// ---------------- K2: particle encoder + hoisted pp_w top-half ----------------
// 256 thr = 4 node-groups x 64 channels; 16 nodes/block; grid = 256
__global__ __launch_bounds__(256) void k_penc(
    const float* __restrict__ s_delta, const float* __restrict__ a_cur,
    const float* __restrict__ pe_w1, const float* __restrict__ pe_b1,
    const float* __restrict__ pe_w2, const float* __restrict__ pe_b2,
    const float* __restrict__ pp_w,  const float* __restrict__ pp_b)
{
    __shared__ float w1[12*NF], w2[NF*NF], wq[NF*NF];
    __shared__ float b1[NF], b2[NF], bq[NF];
    __shared__ float pin[4][12];
    __shared__ float hb[4][NF];
    for (int t = threadIdx.x; t < 12*NF; t += 256) w1[t] = pe_w1[t];
    for (int t = threadIdx.x; t < NF*NF; t += 256) w2[t] = pe_w2[t];
    for (int t = threadIdx.x; t < NF*NF; t += 256) wq[t] = pp_w[t]; // rows 0..63
    if (threadIdx.x < NF) {
        b1[threadIdx.x] = pe_b1[threadIdx.x];
        b2[threadIdx.x] = pe_b2[threadIdx.x];
        bq[threadIdx.x] = pp_b[threadIdx.x];
    }
    __syncthreads();

    int g = threadIdx.x >> 6;
    int c = threadIdx.x & 63;
    for (int it = 0; it < 4; ++it) {
        int node = blockIdx.x*16 + it*4 + g;
        int b = node / NN, n = node % NN;
        if (c < 12)
            pin[g][c] = (c < 9) ? s_delta[((size_t)b*9 + c)*NN + n]
                                : a_cur[b*NN + n];
        __syncthreads();
        float acc = b1[c];
#pragma unroll
        for (int r = 0; r < 12; r++) acc = fmaf(pin[g][r], w1[r*NF+c], acc);
        hb[g][c] = fmaxf(acc, 0.f);
        __syncthreads();
        acc = b2[c];
#pragma unroll 16
        for (int r = 0; r < NF; r++) acc = fmaf(hb[g][r], w2[r*NF+c], acc);
        float pe = fmaxf(acc, 0.f);
        g_penc[(size_t)node*NF + c] = pe;
        g_eff0[(size_t)node*NF + c] = pe;   // effect init = p_enc
        __syncthreads();
        hb[g][c] = pe;
        __syncthreads();
        acc = bq[c];
#pragma unroll 16
        for (int r = 0; r < NF; r++) acc = fmaf(hb[g][r], wq[r*NF+c], acc);
        g_q[(size_t)node*NF + c] = acc;
        __syncthreads();
    }
}

// ---------------- K3a: relation encoder (5->64->64->64) ----------------
// 256 thr = 4 edge-groups x 64 channels; 32 edges/block; grid = NE/32 = 1024
__global__ __launch_bounds__(256) void k_rel(
    const float* __restrict__ states, const float* __restrict__ a_cur,
    const float* __restrict__ re_w1, const float* __restrict__ re_b1,
    const float* __restrict__ re_w2, const float* __restrict__ re_b2,
    const float* __restrict__ re_w3, const float* __restrict__ re_b3)
{
    __shared__ float w1[5*NF], w2[NF*NF], w3[NF*NF];
    __shared__ float b1[NF], b2[NF], b3[NF];
    __shared__ float rin[4][5];
    __shared__ float hb[4][NF];
    for (int t = threadIdx.x; t < 5*NF;  t += 256) w1[t] = re_w1[t];
    for (int t = threadIdx.x; t < NF*NF; t += 256) w2[t] = re_w2[t];
    for (int t = threadIdx.x; t < NF*NF; t += 256) w3[t] = re_w3[t];
    if (threadIdx.x < NF) {
        b1[threadIdx.x] = re_b1[threadIdx.x];
        b2[threadIdx.x] = re_b2[threadIdx.x];
        b3[threadIdx.x] = re_b3[threadIdx.x];
    }
    __syncthreads();

    int g = threadIdx.x >> 6;
    int c = threadIdx.x & 63;
    for (int it = 0; it < 8; ++it) {
        int e = blockIdx.x*32 + it*4 + g;
        int node = e >> 3;
        int b = node / NN, i = node % NN;
        int j = g_send[e];
        int jj = j < 0 ? 0 : j;
        if (c < 5) {
            float v;
            if (c == 0)      v = a_cur[b*NN + i];
            else if (c == 1) v = a_cur[b*NN + jj];
            else v = states[((size_t)b*NN + i )*3 + (c-2)]
                   - states[((size_t)b*NN + jj)*3 + (c-2)];
            rin[g][c] = v;
        }
        __syncthreads();
        float acc = b1[c];
#pragma unroll
        for (int r = 0; r < 5; r++) acc = fmaf(rin[g][r], w1[r*NF+c], acc);
        hb[g][c] = fmaxf(acc, 0.f);
        __syncthreads();
        acc = b2[c];
#pragma unroll 16
        for (int r = 0; r < NF; r++) acc = fmaf(hb[g][r], w2[r*NF+c], acc);
        float h2 = fmaxf(acc, 0.f);
        __syncthreads();
        hb[g][c] = h2;
        __syncthreads();
        acc = b3[c];
#pragma unroll 16
        for (int r = 0; r < NF; r++) acc = fmaf(hb[g][r], w3[r*NF+c], acc);
        g_A[(size_t)e*NF + c] = (j < 0) ? 0.f : fmaxf(acc, 0.f);
        __syncthreads();
    }
}

// ---------------- K3b: hoist A = rel_enc @ rp_w[0:64] + rp_b (in place) ------
__global__ __launch_bounds__(256) void k_relA(
    const float* __restrict__ rp_w, const float* __restrict__ rp_b)
{
    __shared__ float wA[NF*NF];
    __shared__ float bA[NF];
    __shared__ float rel[4][NF];
    for (int t = threadIdx.x; t < NF*NF; t += 256) wA[t] = rp_w[t]; // rows 0..63
    if (threadIdx.x < NF) bA[threadIdx.x] = rp_b[threadIdx.x];
    __syncthreads();

    int g = threadIdx.x >> 6;
    int c = threadIdx.x & 63;
    for (int it = 0; it < 8; ++it) {
        int e = blockIdx.x*32 + it*4 + g;
        rel[g][c] = g_A[(size_t)e*NF + c];
        __syncthreads();
        float acc = bA[c];
#pragma unroll 16
        for (int r = 0; r < NF; r++) acc = fmaf(rel[g][r], wA[r*NF+c], acc);
        g_A[(size_t)e*NF + c] = acc;   // safe: rel fully staged in smem
        __syncthreads();
    }
}

// ---------------- K4: one propagation step ----------------
// 256 thr = 4 node-groups x 64 ch; 16 nodes/block; grid = 256.
// Edge matvecs register-blocked over the 8 edges (1 weight LDS -> 8 FFMA).
__global__ __launch_bounds__(256) void k_prop(
    int which,
    const float* __restrict__ rp_w, const float* __restrict__ pp_w)
{
    const float* effin = (which & 1) ? g_eff1 : g_eff0;
    float*       effout= (which & 1) ? g_eff0 : g_eff1;

    __shared__ float Wr[NF*NF], Ws[NF*NF];
    __shared__ float effi[4][NF];
    __shared__ float effj[4][TK][NF];
    __shared__ float agg[4][NF];
    for (int t = threadIdx.x; t < NF*NF; t += 256) {
        Wr[t] = rp_w[ 64*NF + t];   // receiver block
        Ws[t] = rp_w[128*NF + t];   // sender block
    }
    __syncthreads();

    int g = threadIdx.x >> 6;
    int c = threadIdx.x & 63;
    for (int it = 0; it < 4; ++it) {
        int node = blockIdx.x*16 + it*4 + g;
        int b = node / NN;
        int cnt = g_cnt[node];
        float myeff = effin[(size_t)node*NF + c];
        effi[g][c] = myeff;
#pragma unroll
        for (int k = 0; k < TK; k++) {
            int j = g_send[node*TK + k];
            int jj = j < 0 ? 0 : j;
            effj[g][k][c] = (j >= 0) ? effin[((size_t)b*NN + jj)*NF + c] : 0.f;
        }
        __syncthreads();

        float tacc = 0.f;
#pragma unroll 16
        for (int r = 0; r < NF; r++) tacc = fmaf(effi[g][r], Wr[r*NF+c], tacc);

        float a[TK];
#pragma unroll
        for (int k = 0; k < TK; k++)
            a[k] = g_A[((size_t)node*TK + k)*NF + c] + tacc;

#pragma unroll 8
        for (int r = 0; r < NF; r++) {
            float w = Ws[r*NF+c];
#pragma unroll
            for (int k = 0; k < TK; k++)
                a[k] = fmaf(w, effj[g][k][r], a[k]);
        }
        float s = 0.f;
#pragma unroll
        for (int k = 0; k < TK; k++)
            if (k < cnt) s += fmaxf(a[k], 0.f);
        agg[g][c] = s;
        __syncthreads();

        float acc = g_q[(size_t)node*NF + c] + myeff;
#pragma unroll 16
        for (int r = 0; r < NF; r++)
            acc = fmaf(agg[g][r], __ldg(&pp_w[(size_t)(64+r)*NF + c]), acc);
        effout[(size_t)node*NF + c] = fmaxf(acc, 0.f);
        __syncthreads();
    }
}

// ---------------- K5: predictor + residual add ----------------
__global__ __launch_bounds__(256) void k_pred(
    const float* __restrict__ states,
    const float* __restrict__ pr_w1, const float* __restrict__ pr_b1,
    const float* __restrict__ pr_w2, const float* __restrict__ pr_b2,
    float* __restrict__ out)
{
    __shared__ float W1[NF*NF], b1[NF];
    __shared__ float W2[NF*3],  b2[3];
    __shared__ float ef[4][NF], hh[4][NF];
    for (int t = threadIdx.x; t < NF*NF; t += 256) W1[t] = pr_w1[t];
    for (int t = threadIdx.x; t < NF*3;  t += 256) W2[t] = pr_w2[t];
    if (threadIdx.x < NF) b1[threadIdx.x] = pr_b1[threadIdx.x];
    if (threadIdx.x < 3)  b2[threadIdx.x] = pr_b2[threadIdx.x];
    __syncthreads();

    int g = threadIdx.x >> 6;
    int c = threadIdx.x & 63;
    for (int it = 0; it < 4; ++it) {
        int node = blockIdx.x*16 + it*4 + g;
        ef[g][c] = g_eff1[(size_t)node*NF + c];   // final effect lives in eff1
        __syncthreads();
        float acc = b1[c];
#pragma unroll 16
        for (int r = 0; r < NF; r++) acc = fmaf(ef[g][r], W1[r*NF+c], acc);
        hh[g][c] = fmaxf(acc, 0.f);
        __syncthreads();
        if (c < 3) {
            float p = b2[c];
#pragma unroll 16
            for (int r = 0; r < NF; r++) p = fmaf(hh[g][r], W2[r*3+c], p);
            out[(size_t)node*3 + c] = states[(size_t)node*3 + c] + p;
        }
        __syncthreads();
    }
}

// ---------------- launch ----------------
extern "C" void kernel_launch(void* const* d_in, const int* in_sizes, int n_in,
                              void* d_out, int out_size)
{
    const float* states  = (const float*)d_in[0];
    const float* a_cur   = (const float*)d_in[1];
    const float* s_delta = (const float*)d_in[2];
    const unsigned char* mask  = (const unsigned char*)d_in[3];
    const unsigned char* tmask = (const unsigned char*)d_in[4];
    // Weight block starts at 6 when the scalar `topk` is materialized as an
    // input (in_sizes[5]==1), otherwise at 5.
    int wbase = (n_in > 5 && in_sizes[5] == 1) ? 6 : 5;
    const float* pe_w1 = (const float*)d_in[wbase + 0];
    const float* pe_b1 = (const float*)d_in[wbase + 1];
    const float* pe_w2 = (const float*)d_in[wbase + 2];
    const float* pe_b2 = (const float*)d_in[wbase + 3];
    const float* re_w1 = (const float*)d_in[wbase + 4];
    const float* re_b1 = (const float*)d_in[wbase + 5];
    const float* re_w2 = (const float*)d_in[wbase + 6];
    const float* re_b2 = (const float*)d_in[wbase + 7];
    const float* re_w3 = (const float*)d_in[wbase + 8];
    const float* re_b3 = (const float*)d_in[wbase + 9];
    const float* rp_w  = (const float*)d_in[wbase + 10];
    const float* rp_b  = (const float*)d_in[wbase + 11];
    const float* pp_w  = (const float*)d_in[wbase + 12];
    const float* pp_b  = (const float*)d_in[wbase + 13];
    const float* pr_w1 = (const float*)d_in[wbase + 14];
    const float* pr_b1 = (const float*)d_in[wbase + 15];
    const float* pr_w2 = (const float*)d_in[wbase + 16];
    const float* pr_b2 = (const float*)d_in[wbase + 17];
    float* out = (float*)d_out;

    k_masks<<<(NNODES + 255)/256, 256>>>(mask, tmask);
    k_edges<<<NNODES/8, 256>>>(states);
    k_penc <<<NNODES/16, 256>>>(s_delta, a_cur, pe_w1, pe_b1, pe_w2, pe_b2,
                                pp_w, pp_b);
    k_rel  <<<NE/32, 256>>>(states, a_cur, re_w1, re_b1, re_w2, re_b2,
                            re_w3, re_b3);
    k_relA <<<NE/32, 256>>>(rp_w, rp_b);
    k_prop <<<NNODES/16, 256>>>(0, rp_w, pp_w);  // eff0 -> eff1
    k_prop <<<NNODES/16, 256>>>(1, rp_w, pp_w);  // eff1 -> eff0
    k_prop <<<NNODES/16, 256>>>(2, rp_w, pp_w);  // eff0 -> eff1
    k_pred <<<NNODES/16, 256>>>(states, pr_w1, pr_b1, pr_w2, pr_b2, out);
}

// round 3
// speedup vs baseline: 1.3112x; 1.3112x over previous
#include <cuda_runtime.h>
#include <stdint.h>

#define BB 2
#define NN 2048
#define TK 8
#define NF 64
#define NNODES (BB*NN)
#define NE (NNODES*TK)

// ---------------- packed-fp32 (FFMA2) helpers ----------------
#define FMA2(acc, a, b) \
    asm("fma.rn.f32x2 %0, %1, %2, %0;" : "+l"(acc) : "l"(a), "l"(b))
#define ADD2(acc, a) \
    asm("add.rn.f32x2 %0, %0, %1;" : "+l"(acc) : "l"(a))
#define DUP2(d, v) \
    asm("mov.b64 %0, {%1, %1};" : "=l"(d) : "f"(v))
#define PACK2(d, lo, hi) \
    asm("mov.b64 %0, {%1, %2};" : "=l"(d) : "f"(lo), "f"(hi))
#define UNPK2(lo, hi, v) \
    asm("mov.b64 {%0, %1}, %2;" : "=f"(lo), "=f"(hi) : "l"(v))

// ---------------- device scratch (no allocations allowed) ----------------
__device__ unsigned char g_mask[NNODES];
__device__ unsigned char g_tmask[NNODES];
__device__ int   g_send[NE];          // sender idx within batch, -1 = invalid
__device__ int   g_cnt[NNODES];       // # valid edges per receiver (prefix)
__device__ float g_A[NE*NF];          // rel_enc @ rp_w[0:64] + rp_b (hoisted)
__device__ float g_penc[NNODES*NF];   // particle encoder output
__device__ float g_q[NNODES*NF];      // pp_w[0:64]^T p_enc + pp_b
__device__ float g_eff0[NNODES*NF];
__device__ float g_eff1[NNODES*NF];

// ---------------- K0: normalize masks (runtime dtype detection) -------------
__device__ __forceinline__ unsigned char mask_elem(const unsigned char* p, int i) {
    unsigned w0 = *(const unsigned*)p;
    if (w0 == 0x01010101u)            return p[i] != 0;                    // u8/bool
    if (w0 == 0x3f800000u)            return ((const float*)p)[i] != 0.f;  // f32
    /* default int32 */               return ((const int*)p)[i] != 0;      // i32
}
__global__ __launch_bounds__(256) void k_masks(
    const unsigned char* __restrict__ mask_raw,
    const unsigned char* __restrict__ tmask_raw)
{
    int i = blockIdx.x*256 + threadIdx.x;
    if (i < NNODES) {
        g_mask[i]  = mask_elem(mask_raw, i);
        g_tmask[i] = mask_elem(tmask_raw, i);
    }
}

// ---------------- K1: edge construction (8-NN with threshold) ----------------
__global__ __launch_bounds__(256) void k_edges(
    const float* __restrict__ states)
{
    __shared__ float s_st[NN*3];
    __shared__ unsigned char s_m[NN];
    int b  = blockIdx.x / (NN/8);
    int i0 = (blockIdx.x % (NN/8)) * 8;
    const float* stb = states + (size_t)b*NN*3;
    for (int t = threadIdx.x; t < NN*3; t += 256) s_st[t] = stb[t];
    for (int t = threadIdx.x; t < NN;   t += 256) s_m[t]  = g_mask[b*NN + t];
    __syncthreads();

    const float TH2 = 0.12f * 0.12f;

    int w = threadIdx.x >> 5, lane = threadIdx.x & 31;
    int i = i0 + w;
    int node = b*NN + i;
    bool recv_ok = (g_mask[node] != 0) && (g_tmask[node] == 0);

    unsigned long long keys[TK];
#pragma unroll
    for (int k = 0; k < TK; k++) keys[k] = ~0ULL;

    if (recv_ok) {
        float xi = s_st[i*3+0], yi = s_st[i*3+1], zi = s_st[i*3+2];
        unsigned long long curmax = ~0ULL; int maxslot = 0;
        for (int j = lane; j < NN; j += 32) {
            float dx = xi - s_st[j*3+0];
            float dy = yi - s_st[j*3+1];
            float dz = zi - s_st[j*3+2];
            float d2 = fmaf(dx, dx, fmaf(dy, dy, dz*dz));
            if (!s_m[j]) d2 = 1e10f;
            unsigned long long key =
                ((unsigned long long)__float_as_uint(d2) << 32) | (unsigned)j;
            if (key < curmax) {
                keys[maxslot] = key;
                curmax = keys[0]; maxslot = 0;
#pragma unroll
                for (int k = 1; k < TK; k++)
                    if (keys[k] > curmax) { curmax = keys[k]; maxslot = k; }
            }
        }
    }

    int cnt = 0;
#pragma unroll 1
    for (int r = 0; r < TK; r++) {
        unsigned long long mymin = keys[0]; int mslot = 0;
#pragma unroll
        for (int k = 1; k < TK; k++)
            if (keys[k] < mymin) { mymin = keys[k]; mslot = k; }
        unsigned long long v = mymin;
#pragma unroll
        for (int off = 16; off; off >>= 1) {
            unsigned long long o = __shfl_down_sync(0xffffffffu, v, off);
            if (o < v) v = o;
        }
        v = __shfl_sync(0xffffffffu, v, 0);
        if (v == mymin && v != ~0ULL) keys[mslot] = ~0ULL;
        if (lane == 0) {
            float d2 = __uint_as_float((unsigned)(v >> 32));
            int j = (int)(v & 0xffffffffULL);
            bool valid = (v != ~0ULL) && (d2 < TH2);
            g_send[node*TK + r] = valid ? j : -1;
            cnt += valid ? 1 : 0;
        }
    }
    if (lane == 0) g_cnt[node] = cnt;
}

// ---------------- K2: particle encoder + hoisted pp_w top-half ----------------
__global__ __launch_bounds__(256) void k_penc(
    const float* __restrict__ s_delta, const float* __restrict__ a_cur,
    const float* __restrict__ pe_w1, const float* __restrict__ pe_b1,
    const float* __restrict__ pe_w2, const float* __restrict__ pe_b2,
    const float* __restrict__ pp_w,  const float* __restrict__ pp_b)
{
    __shared__ float w1[12*NF], w2[NF*NF], wq[NF*NF];
    __shared__ float b1[NF], b2[NF], bq[NF];
    __shared__ float pin[4][12];
    __shared__ float hb[4][NF];
    for (int t = threadIdx.x; t < 12*NF; t += 256) w1[t] = pe_w1[t];
    for (int t = threadIdx.x; t < NF*NF; t += 256) w2[t] = pe_w2[t];
    for (int t = threadIdx.x; t < NF*NF; t += 256) wq[t] = pp_w[t]; // rows 0..63
    if (threadIdx.x < NF) {
        b1[threadIdx.x] = pe_b1[threadIdx.x];
        b2[threadIdx.x] = pe_b2[threadIdx.x];
        bq[threadIdx.x] = pp_b[threadIdx.x];
    }
    __syncthreads();

    int g = threadIdx.x >> 6;
    int c = threadIdx.x & 63;
    for (int it = 0; it < 4; ++it) {
        int node = blockIdx.x*16 + it*4 + g;
        int b = node / NN, n = node % NN;
        if (c < 12)
            pin[g][c] = (c < 9) ? s_delta[((size_t)b*9 + c)*NN + n]
                                : a_cur[b*NN + n];
        __syncthreads();
        float acc = b1[c];
#pragma unroll
        for (int r = 0; r < 12; r++) acc = fmaf(pin[g][r], w1[r*NF+c], acc);
        hb[g][c] = fmaxf(acc, 0.f);
        __syncthreads();
        acc = b2[c];
#pragma unroll 16
        for (int r = 0; r < NF; r++) acc = fmaf(hb[g][r], w2[r*NF+c], acc);
        float pe = fmaxf(acc, 0.f);
        g_penc[(size_t)node*NF + c] = pe;
        g_eff0[(size_t)node*NF + c] = pe;
        __syncthreads();
        hb[g][c] = pe;
        __syncthreads();
        acc = bq[c];
#pragma unroll 16
        for (int r = 0; r < NF; r++) acc = fmaf(hb[g][r], wq[r*NF+c], acc);
        g_q[(size_t)node*NF + c] = acc;
        __syncthreads();
    }
}

// ---------------- K3: relation encoder, edge-per-thread, FFMA2, fused relA ---
// 128 threads/block, 1 edge per thread, grid = NE/128 = 256.
// dyn smem: sw1[320] | sw2,sw3,swA[3*4096] | sb1[64] | sb2,sb3,sbA[3*64]
__global__ __launch_bounds__(128) void k_rel(
    const float* __restrict__ states, const float* __restrict__ a_cur,
    const float* __restrict__ re_w1, const float* __restrict__ re_b1,
    const float* __restrict__ re_w2, const float* __restrict__ re_b2,
    const float* __restrict__ re_w3, const float* __restrict__ re_b3,
    const float* __restrict__ rp_w,  const float* __restrict__ rp_b)
{
    extern __shared__ float dsm[];
    float* sw1 = dsm;              // 5*64 = 320
    float* swb = dsm + 320;        // 3 big mats: 3*4096
    float* sb1 = dsm + 320 + 3*4096;     // 64
    float* sbb = sb1 + 64;               // 3*64

    for (int t = threadIdx.x; t < 5*NF; t += 128) sw1[t] = re_w1[t];
    for (int t = threadIdx.x; t < NF*NF; t += 128) {
        swb[t]        = re_w2[t];
        swb[4096 + t] = re_w3[t];
        swb[8192 + t] = rp_w[t];     // rows 0..63 of rp_w
    }
    if (threadIdx.x < NF) {
        sb1[threadIdx.x]       = re_b1[threadIdx.x];
        sbb[threadIdx.x]       = re_b2[threadIdx.x];
        sbb[64 + threadIdx.x]  = re_b3[threadIdx.x];
        sbb[128 + threadIdx.x] = rp_b[threadIdx.x];
    }
    __syncthreads();

    int e = blockIdx.x*128 + threadIdx.x;
    int node = e >> 3;
    int b = node / NN, i = node % NN;
    int j = g_send[e];
    int jj = j < 0 ? 0 : j;

    float rin[5];
    rin[0] = a_cur[b*NN + i];
    rin[1] = a_cur[b*NN + jj];
#pragma unroll
    for (int d = 0; d < 3; d++)
        rin[2+d] = states[((size_t)b*NN + i)*3 + d]
                 - states[((size_t)b*NN + jj)*3 + d];

    float h[64];
    // ---- L1: 5 -> 64 (scalar FMA, small) ----
#pragma unroll
    for (int c4 = 0; c4 < 16; c4++) {
        float4 acc = *(const float4*)&sb1[c4*4];
#pragma unroll
        for (int r = 0; r < 5; r++) {
            float4 w = *(const float4*)&sw1[r*64 + c4*4];
            float x = rin[r];
            acc.x = fmaf(x, w.x, acc.x); acc.y = fmaf(x, w.y, acc.y);
            acc.z = fmaf(x, w.z, acc.z); acc.w = fmaf(x, w.w, acc.w);
        }
        h[c4*4+0] = fmaxf(acc.x, 0.f); h[c4*4+1] = fmaxf(acc.y, 0.f);
        h[c4*4+2] = fmaxf(acc.z, 0.f); h[c4*4+3] = fmaxf(acc.w, 0.f);
    }

    // ---- L2 (re_w2, relu), L3 (re_w3, relu), L4 (rp_w[0:64]+rp_b, no relu) ----
    const float* wb = swb;
    const float* bb = sbb;
#pragma unroll 1
    for (int layer = 0; layer < 3; layer++) {
        unsigned long long acc2[32];
#pragma unroll
        for (int p = 0; p < 32; p++) PACK2(acc2[p], bb[2*p], bb[2*p+1]);
#pragma unroll
        for (int r = 0; r < 64; r++) {
            unsigned long long hd; DUP2(hd, h[r]);
#pragma unroll
            for (int c4 = 0; c4 < 16; c4++) {
                ulonglong2 w = *(const ulonglong2*)(wb + r*64 + c4*4);
                FMA2(acc2[c4*2],   w.x, hd);
                FMA2(acc2[c4*2+1], w.y, hd);
            }
        }
        if (layer < 2) {
#pragma unroll
            for (int p = 0; p < 32; p++) {
                float lo, hi; UNPK2(lo, hi, acc2[p]);
                h[2*p]   = fmaxf(lo, 0.f);
                h[2*p+1] = fmaxf(hi, 0.f);
            }
        } else {
            float* dst = g_A + (size_t)e*64;
#pragma unroll
            for (int c4 = 0; c4 < 16; c4++) {
                float x0,x1,x2,x3;
                UNPK2(x0, x1, acc2[c4*2]);
                UNPK2(x2, x3, acc2[c4*2+1]);
                *(float4*)(dst + c4*4) = make_float4(x0,x1,x2,x3);
            }
        }
        wb += 4096; bb += 64;
    }
}

// ---------------- K4: one propagation step (warp-per-node, FFMA2) ----------
// 256 thr = 8 warps; each warp: 1 node per pass, 2 passes; grid = 256.
// Lane c handles channels (2c, 2c+1).
// dyn smem floats: sWr[4096] sWs[4096] sWp[4096] (pair-major)
//                  s_effi[8][128](dup) s_ej[8][8*128](dup) s_agg[8][128](dup)
__global__ __launch_bounds__(256) void k_prop(
    int which,
    const float* __restrict__ rp_w, const float* __restrict__ pp_w)
{
    const float* effin = (which & 1) ? g_eff1 : g_eff0;
    float*       effout= (which & 1) ? g_eff0 : g_eff1;

    extern __shared__ float dsm[];
    float* sWr = dsm;
    float* sWs = dsm + 4096;
    float* sWp = dsm + 8192;
    float* sEi = dsm + 12288;            // 8 warps * 128
    float* sEj = dsm + 12288 + 1024;     // 8 warps * 1024
    float* sAg = dsm + 12288 + 1024 + 8192;  // 8 warps * 128

    // load weights pair-major: elem (r,c) -> [r/2]*128 + (c/2)*4 + (r&1)*2 + (c&1)
    for (int idx = threadIdx.x; idx < 4096; idx += 256) {
        int r = idx >> 6, cc = idx & 63;
        int off = (r>>1)*128 + (cc>>1)*4 + (r&1)*2 + (cc&1);
        sWr[off] = rp_w[(size_t)( 64 + r)*64 + cc];
        sWs[off] = rp_w[(size_t)(128 + r)*64 + cc];
        sWp[off] = pp_w[(size_t)( 64 + r)*64 + cc];
    }
    __syncthreads();

    int w = threadIdx.x >> 5, lane = threadIdx.x & 31;
    float* ei = sEi + w*128;
    float* ej = sEj + w*1024;
    float* ag = sAg + w*128;

#pragma unroll 1
    for (int pass = 0; pass < 2; pass++) {
        int node = blockIdx.x*16 + pass*8 + w;
        int bN = (node / NN) * NN;
        int cnt = g_cnt[node];

        // senders
        int sjv = 0;
        if (lane < TK) { int j = g_send[node*TK + lane]; sjv = j < 0 ? 0 : j; }

        // my channels: effect, q
        unsigned long long me2 = *(const unsigned long long*)
            &effin[(size_t)node*64 + 2*lane];
        unsigned long long q2 = *(const unsigned long long*)
            &g_q[(size_t)node*64 + 2*lane];
        // A accumulators
        unsigned long long a2[TK];
#pragma unroll
        for (int k = 0; k < TK; k++)
            a2[k] = *(const unsigned long long*)
                &g_A[((size_t)node*TK + k)*64 + 2*lane];

        // prefetch effi dup
        if (lane < 16) {
            float4 v = *(const float4*)&effin[(size_t)node*64 + lane*4];
            *(float4*)&ei[lane*8]     = make_float4(v.x,v.x,v.y,v.y);
            *(float4*)&ei[lane*8 + 4] = make_float4(v.z,v.z,v.w,v.w);
        }
        // prefetch effj dup (8 rows x 16 float4)
#pragma unroll
        for (int t = 0; t < 4; t++) {
            int f = lane + t*32;
            int k = f >> 4, part = f & 15;
            int sj = __shfl_sync(0xffffffffu, sjv, k);
            float4 v = *(const float4*)&effin[((size_t)bN + sj)*64 + part*4];
            *(float4*)&ej[k*128 + part*8]     = make_float4(v.x,v.x,v.y,v.y);
            *(float4*)&ej[k*128 + part*8 + 4] = make_float4(v.z,v.z,v.w,v.w);
        }
        __syncwarp();

        // tacc = Wr^T effi  (packed 2 channels)
        unsigned long long tacc; DUP2(tacc, 0.f);
#pragma unroll 8
        for (int r2 = 0; r2 < 32; r2++) {
            ulonglong2 wv = *(const ulonglong2*)&sWr[r2*128 + lane*4];
            ulonglong2 ev = *(const ulonglong2*)&ei[r2*4];
            FMA2(tacc, wv.x, ev.x);
            FMA2(tacc, wv.y, ev.y);
        }
#pragma unroll
        for (int k = 0; k < TK; k++) ADD2(a2[k], tacc);

        // a2[k] += Ws^T effj_k
#pragma unroll 8
        for (int r2 = 0; r2 < 32; r2++) {
            ulonglong2 wv = *(const ulonglong2*)&sWs[r2*128 + lane*4];
#pragma unroll
            for (int k = 0; k < TK; k++) {
                ulonglong2 ev = *(const ulonglong2*)&ej[k*128 + r2*4];
                FMA2(a2[k], wv.x, ev.x);
                FMA2(a2[k], wv.y, ev.y);
            }
        }

        // masked relu-sum over valid edges
        float s0 = 0.f, s1 = 0.f;
#pragma unroll
        for (int k = 0; k < TK; k++) {
            float lo, hi; UNPK2(lo, hi, a2[k]);
            if (k < cnt) { s0 += fmaxf(lo, 0.f); s1 += fmaxf(hi, 0.f); }
        }
        *(float4*)&ag[lane*4] = make_float4(s0, s0, s1, s1);
        __syncwarp();

        // out = relu(q + myeff + Wp^T agg)
        unsigned long long out2 = q2;
        ADD2(out2, me2);
#pragma unroll 8
        for (int r2 = 0; r2 < 32; r2++) {
            ulonglong2 wv = *(const ulonglong2*)&sWp[r2*128 + lane*4];
            ulonglong2 av = *(const ulonglong2*)&ag[r2*4];
            FMA2(out2, wv.x, av.x);
            FMA2(out2, wv.y, av.y);
        }
        float o0, o1; UNPK2(o0, o1, out2);
        *(float2*)&effout[(size_t)node*64 + 2*lane] =
            make_float2(fmaxf(o0, 0.f), fmaxf(o1, 0.f));
        __syncwarp();
    }
}

// ---------------- K5: predictor + residual add ----------------
__global__ __launch_bounds__(256) void k_pred(
    const float* __restrict__ states,
    const float* __restrict__ pr_w1, const float* __restrict__ pr_b1,
    const float* __restrict__ pr_w2, const float* __restrict__ pr_b2,
    float* __restrict__ out)
{
    __shared__ float W1[NF*NF], b1[NF];
    __shared__ float W2[NF*3],  b2[3];
    __shared__ float ef[4][NF], hh[4][NF];
    for (int t = threadIdx.x; t < NF*NF; t += 256) W1[t] = pr_w1[t];
    for (int t = threadIdx.x; t < NF*3;  t += 256) W2[t] = pr_w2[t];
    if (threadIdx.x < NF) b1[threadIdx.x] = pr_b1[threadIdx.x];
    if (threadIdx.x < 3)  b2[threadIdx.x] = pr_b2[threadIdx.x];
    __syncthreads();

    int g = threadIdx.x >> 6;
    int c = threadIdx.x & 63;
    for (int it = 0; it < 4; ++it) {
        int node = blockIdx.x*16 + it*4 + g;
        ef[g][c] = g_eff1[(size_t)node*NF + c];
        __syncthreads();
        float acc = b1[c];
#pragma unroll 16
        for (int r = 0; r < NF; r++) acc = fmaf(ef[g][r], W1[r*NF+c], acc);
        hh[g][c] = fmaxf(acc, 0.f);
        __syncthreads();
        if (c < 3) {
            float p = b2[c];
#pragma unroll 16
            for (int r = 0; r < NF; r++) p = fmaf(hh[g][r], W2[r*3+c], p);
            out[(size_t)node*3 + c] = states[(size_t)node*3 + c] + p;
        }
        __syncthreads();
    }
}

// ---------------- launch ----------------
extern "C" void kernel_launch(void* const* d_in, const int* in_sizes, int n_in,
                              void* d_out, int out_size)
{
    const float* states  = (const float*)d_in[0];
    const float* a_cur   = (const float*)d_in[1];
    const float* s_delta = (const float*)d_in[2];
    const unsigned char* mask  = (const unsigned char*)d_in[3];
    const unsigned char* tmask = (const unsigned char*)d_in[4];
    int wbase = (n_in > 5 && in_sizes[5] == 1) ? 6 : 5;
    const float* pe_w1 = (const float*)d_in[wbase + 0];
    const float* pe_b1 = (const float*)d_in[wbase + 1];
    const float* pe_w2 = (const float*)d_in[wbase + 2];
    const float* pe_b2 = (const float*)d_in[wbase + 3];
    const float* re_w1 = (const float*)d_in[wbase + 4];
    const float* re_b1 = (const float*)d_in[wbase + 5];
    const float* re_w2 = (const float*)d_in[wbase + 6];
    const float* re_b2 = (const float*)d_in[wbase + 7];
    const float* re_w3 = (const float*)d_in[wbase + 8];
    const float* re_b3 = (const float*)d_in[wbase + 9];
    const float* rp_w  = (const float*)d_in[wbase + 10];
    const float* rp_b  = (const float*)d_in[wbase + 11];
    const float* pp_w  = (const float*)d_in[wbase + 12];
    const float* pp_b  = (const float*)d_in[wbase + 13];
    const float* pr_w1 = (const float*)d_in[wbase + 14];
    const float* pr_b1 = (const float*)d_in[wbase + 15];
    const float* pr_w2 = (const float*)d_in[wbase + 16];
    const float* pr_b2 = (const float*)d_in[wbase + 17];
    float* out = (float*)d_out;

    const int REL_SMEM  = (320 + 3*4096 + 64 + 3*64) * 4;       // 51456 B
    const int PROP_SMEM = (3*4096 + 8*128 + 8*1024 + 8*128) * 4; // 90112 B
    static int attr_done = 0;
    if (!attr_done) {
        cudaFuncSetAttribute(k_rel,  cudaFuncAttributeMaxDynamicSharedMemorySize, REL_SMEM);
        cudaFuncSetAttribute(k_prop, cudaFuncAttributeMaxDynamicSharedMemorySize, PROP_SMEM);
        attr_done = 1;
    }

    k_masks<<<(NNODES + 255)/256, 256>>>(mask, tmask);
    k_edges<<<NNODES/8, 256>>>(states);
    k_penc <<<NNODES/16, 256>>>(s_delta, a_cur, pe_w1, pe_b1, pe_w2, pe_b2,
                                pp_w, pp_b);
    k_rel  <<<NE/128, 128, REL_SMEM>>>(states, a_cur,
                                       re_w1, re_b1, re_w2, re_b2,
                                       re_w3, re_b3, rp_w, rp_b);
    k_prop <<<NNODES/16, 256, PROP_SMEM>>>(0, rp_w, pp_w);  // eff0 -> eff1
    k_prop <<<NNODES/16, 256, PROP_SMEM>>>(1, rp_w, pp_w);  // eff1 -> eff0
    k_prop <<<NNODES/16, 256, PROP_SMEM>>>(2, rp_w, pp_w);  // eff0 -> eff1
    k_pred <<<NNODES/16, 256>>>(states, pr_w1, pr_b1, pr_w2, pr_b2, out);
}